// round 1
// baseline (speedup 1.0000x reference)
#include <cuda_runtime.h>
#include <math.h>

// Problem constants
constexpr int BB    = 8;      // batch
constexpr int NTOK  = 4096;   // tokens (64x64)
constexpr int CD    = 512;    // channels
constexpr int NHEAD = 8;
constexpr int HDIM  = 64;
constexpr int RP    = 8;      // reduction ratio
constexpr int MT    = 64;     // reduced tokens (8x8)
constexpr int KIM   = RP * RP * CD;  // 32768 im2col K
constexpr int SPLITK = 32;

// ---------------- device scratch (no allocations allowed) ----------------
__device__ float g_q[BB * NHEAD * NTOK * HDIM];        // 64 MB  [b,nh,n,hd]
__device__ float g_patch[(size_t)BB * MT * KIM];       // 64 MB  im2col
__device__ float g_part[(size_t)SPLITK * BB * MT * CD];// 33 MB  conv partials
__device__ float g_fmap[BB * MT * CD];                 // conv out
__device__ float g_ln[BB * MT * CD];                   // layernorm out
__device__ float g_kv[BB * MT * 2 * CD];               // kv = ln @ Wkv
__device__ float g_attn[(size_t)BB * NTOK * CD];       // 64 MB  attention out [b,n,c]

// ---------------- generic register-tiled SGEMM ----------------
// C[M,N] = A[M,K] @ B[K,N], row-major. Requires M%BM==0, N%BN==0,
// (K/gridDim.z)%BK==0, K%4==0, N%4==0.
// MODE 0: plain store (+bias).  MODE 1: store partial to C + z*(M*N).
// MODE 2: q-layout store: row=(b,n), col=c -> [b, c%8(head), n, c/8(hd)]
template <int BM, int BN, int BK, int TM, int TN, int MODE>
__global__ __launch_bounds__((BM / TM) * (BN / TN))
void sgemm_k(const float* __restrict__ A, const float* __restrict__ Bm,
             float* __restrict__ C, int M, int N, int K,
             const float* __restrict__ bias)
{
    constexpr int NT = (BM / TM) * (BN / TN);
    __shared__ float As[BK][BM];
    __shared__ float Bs[BK][BN];

    const int tid = threadIdx.x;
    const int bx = blockIdx.x, by = blockIdx.y;
    const int kChunk = K / gridDim.z;
    const int k0 = blockIdx.z * kChunk;

    const int tcol = tid % (BN / TN);
    const int trow = tid / (BN / TN);

    constexpr int AV = BK / 4;
    const int aCol = (tid % AV) * 4;
    const int aRow = tid / AV;
    constexpr int aStride = NT / AV;
    constexpr int BV = BN / 4;
    const int bCol = (tid % BV) * 4;
    const int bRow = tid / BV;
    constexpr int bStride = NT / BV;

    const float* Ab = A + (size_t)by * BM * K;
    const float* Bb = Bm + bx * BN;

    float acc[TM][TN] = {};
    float ra[TM], rb[TN];

    for (int kt = k0; kt < k0 + kChunk; kt += BK) {
#pragma unroll
        for (int r = 0; r < BM; r += aStride) {
            float4 v = *(const float4*)(Ab + (size_t)(aRow + r) * K + kt + aCol);
            As[aCol + 0][aRow + r] = v.x;
            As[aCol + 1][aRow + r] = v.y;
            As[aCol + 2][aRow + r] = v.z;
            As[aCol + 3][aRow + r] = v.w;
        }
#pragma unroll
        for (int r = 0; r < BK; r += bStride) {
            *(float4*)(&Bs[bRow + r][bCol]) =
                *(const float4*)(Bb + (size_t)(kt + bRow + r) * N + bCol);
        }
        __syncthreads();
#pragma unroll
        for (int kk = 0; kk < BK; ++kk) {
#pragma unroll
            for (int i = 0; i < TM; i++) ra[i] = As[kk][trow * TM + i];
#pragma unroll
            for (int j = 0; j < TN; j++) rb[j] = Bs[kk][tcol * TN + j];
#pragma unroll
            for (int i = 0; i < TM; i++)
#pragma unroll
                for (int j = 0; j < TN; j++)
                    acc[i][j] = fmaf(ra[i], rb[j], acc[i][j]);
        }
        __syncthreads();
    }

#pragma unroll
    for (int i = 0; i < TM; i++) {
        int row = by * BM + trow * TM + i;
#pragma unroll
        for (int j = 0; j < TN; j++) {
            int col = bx * BN + tcol * TN + j;
            if (MODE == 0) {
                float v = acc[i][j];
                if (bias) v += bias[col];
                C[(size_t)row * N + col] = v;
            } else if (MODE == 1) {
                C[(size_t)blockIdx.z * M * N + (size_t)row * N + col] = acc[i][j];
            } else {  // MODE 2: q permuted store
                int b  = row >> 12;          // row = b*4096 + n
                int n  = row & 4095;
                int nh = col & 7;            // c = hd*8 + nh
                int hd = col >> 3;
                g_q[(((size_t)(b * NHEAD + nh)) * NTOK + n) * HDIM + hd] = acc[i][j];
            }
        }
    }
}

// ---------------- im2col: x[b, (8i+r)*64+(8j+s), ci] -> patch[b*64+p, (r*8+s)*512+ci]
__global__ void im2col_k(const float* __restrict__ x)
{
    int idx = blockIdx.x * blockDim.x + threadIdx.x;   // float4 index
    int e = idx * 4;
    int pg = e / KIM;
    int kk = e % KIM;
    int b = pg >> 6, p = pg & 63;
    int i = p >> 3, j = p & 7;
    int rs = kk >> 9, ci = kk & 511;
    int r = rs >> 3, s = rs & 7;
    int n = (i * 8 + r) * 64 + (j * 8 + s);
    float4 v = *(const float4*)(x + ((size_t)(b * NTOK + n)) * CD + ci);
    *(float4*)(g_patch + (size_t)pg * KIM + kk) = v;
}

// ---------------- reduce split-K partials (deterministic) ----------------
__global__ void reduce_k()
{
    int i = blockIdx.x * 256 + threadIdx.x;   // 0 .. BB*MT*CD-1
    float s = 0.f;
#pragma unroll
    for (int z = 0; z < SPLITK; z++) s += g_part[(size_t)z * BB * MT * CD + i];
    g_fmap[i] = s;
}

// ---------------- layernorm over C=512 per (b, m) row ----------------
__global__ void ln_k(const float* __restrict__ gamma, const float* __restrict__ beta)
{
    int row = blockIdx.x;
    const float* in = g_fmap + (size_t)row * CD;
    float* out = g_ln + (size_t)row * CD;
    int t = threadIdx.x;              // 256 threads, 2 elems each
    float a = in[t], b2 = in[t + 256];
    float s = a + b2, s2 = a * a + b2 * b2;
#pragma unroll
    for (int o = 16; o; o >>= 1) {
        s  += __shfl_down_sync(0xffffffffu, s,  o);
        s2 += __shfl_down_sync(0xffffffffu, s2, o);
    }
    __shared__ float rs[8], rs2[8];
    int w = t >> 5, l = t & 31;
    if (l == 0) { rs[w] = s; rs2[w] = s2; }
    __syncthreads();
    if (t == 0) {
        float S = 0.f, S2 = 0.f;
        for (int q = 0; q < 8; q++) { S += rs[q]; S2 += rs2[q]; }
        float mu = S / (float)CD;
        float var = S2 / (float)CD - mu * mu;
        rs[0] = mu;
        rs2[0] = rsqrtf(var + 1e-3f);
    }
    __syncthreads();
    float mu = rs[0], inv = rs2[0];
    out[t]       = (a  - mu) * inv * gamma[t]       + beta[t];
    out[t + 256] = (b2 - mu) * inv * gamma[t + 256] + beta[t + 256];
}

// ---------------- attention: per (b,head), K/V (64x64) in SMEM, online softmax
__global__ __launch_bounds__(128) void attn_k()
{
    int bh = blockIdx.y;              // b*8 + nh
    int b = bh >> 3, nh = bh & 7;
    int n = blockIdx.x * 128 + threadIdx.x;

    __shared__ float Ks[MT][HDIM];
    __shared__ float Vs[MT][HDIM];

    // cooperative coalesced load of K/V for this (b,head)
    for (int i = threadIdx.x; i < MT * HDIM / 4; i += 128) {
        int e = i * 4;
        int m = e >> 6, hd = e & 63;
        const float* src = g_kv + ((size_t)(b * MT + m)) * (2 * CD) + nh * HDIM + hd;
        *(float4*)&Ks[m][hd] = *(const float4*)src;
        *(float4*)&Vs[m][hd] = *(const float4*)(src + CD);
    }
    __syncthreads();

    const float* qrow = g_q + ((size_t)bh * NTOK + n) * HDIM;
    float q[HDIM];
#pragma unroll
    for (int i = 0; i < HDIM / 4; i++) {
        float4 v = *(const float4*)(qrow + 4 * i);
        q[4 * i] = v.x; q[4 * i + 1] = v.y; q[4 * i + 2] = v.z; q[4 * i + 3] = v.w;
    }

    float mx = -1e30f, sum = 0.f;
    float o[HDIM];
#pragma unroll
    for (int d = 0; d < HDIM; d++) o[d] = 0.f;

    for (int m = 0; m < MT; m++) {
        float s = 0.f;
#pragma unroll
        for (int d = 0; d < HDIM; d++) s = fmaf(q[d], Ks[m][d], s);
        s *= 0.125f;                  // 1/sqrt(64)
        float nm = fmaxf(mx, s);
        float corr = expf(mx - nm);
        float wgt = expf(s - nm);
        sum = sum * corr + wgt;
#pragma unroll
        for (int d = 0; d < HDIM; d++) o[d] = o[d] * corr + wgt * Vs[m][d];
        mx = nm;
    }
    float inv = 1.f / sum;

    float* dst = g_attn + ((size_t)(b * NTOK + n)) * CD + nh * HDIM;
#pragma unroll
    for (int i = 0; i < HDIM / 4; i++) {
        float4 v;
        v.x = o[4 * i] * inv; v.y = o[4 * i + 1] * inv;
        v.z = o[4 * i + 2] * inv; v.w = o[4 * i + 3] * inv;
        *(float4*)(dst + 4 * i) = v;
    }
}

// ---------------- launch ----------------
extern "C" void kernel_launch(void* const* d_in, const int* in_sizes, int n_in,
                              void* d_out, int out_size)
{
    const float* x     = (const float*)d_in[0];
    const float* Wq    = (const float*)d_in[1];
    const float* Wkv   = (const float*)d_in[2];
    const float* convw = (const float*)d_in[3];
    const float* gamma = (const float*)d_in[4];
    const float* beta  = (const float*)d_in[5];
    const float* Wp    = (const float*)d_in[6];
    const float* bp    = (const float*)d_in[7];
    float* out = (float*)d_out;

    float *q, *patch, *part, *ln, *kv, *attn;
    cudaGetSymbolAddress((void**)&q,     g_q);
    cudaGetSymbolAddress((void**)&patch, g_patch);
    cudaGetSymbolAddress((void**)&part,  g_part);
    cudaGetSymbolAddress((void**)&ln,    g_ln);
    cudaGetSymbolAddress((void**)&kv,    g_kv);
    cudaGetSymbolAddress((void**)&attn,  g_attn);

    // 1. q = x @ Wq  -> permuted [b,nh,n,hd]
    {
        dim3 g(CD / 128, (BB * NTOK) / 128);
        sgemm_k<128, 128, 16, 8, 8, 2><<<g, 256>>>(x, Wq, q, BB * NTOK, CD, CD, nullptr);
    }
    // 2. im2col
    im2col_k<<<(BB * MT * KIM / 4) / 256, 256>>>(x);
    // 3. conv as split-K GEMM: patch[512,32768] @ convw[32768,512] -> partials
    {
        dim3 g(CD / 128, (BB * MT) / 128, SPLITK);
        sgemm_k<128, 128, 16, 8, 8, 1><<<g, 256>>>(patch, convw, part, BB * MT, CD, KIM, nullptr);
    }
    // 4. reduce partials -> g_fmap
    reduce_k<<<(BB * MT * CD) / 256, 256>>>();
    // 5. layernorm -> g_ln
    ln_k<<<BB * MT, 256>>>(gamma, beta);
    // 6. kv = ln @ Wkv  [512, 1024]
    {
        dim3 g((2 * CD) / 64, (BB * MT) / 64);
        sgemm_k<64, 64, 16, 4, 4, 0><<<g, 256>>>(ln, Wkv, kv, BB * MT, 2 * CD, CD, nullptr);
    }
    // 7. attention -> g_attn [b,n,c]
    {
        dim3 g(NTOK / 128, BB * NHEAD);
        attn_k<<<g, 128>>>();
    }
    // 8. out = attn @ Wp + bp
    {
        dim3 g(CD / 128, (BB * NTOK) / 128);
        sgemm_k<128, 128, 16, 8, 8, 0><<<g, 256>>>(attn, Wp, out, BB * NTOK, CD, CD, bp);
    }
}

// round 3
// speedup vs baseline: 2.1137x; 2.1137x over previous
#include <cuda_runtime.h>
#include <math.h>
#include <cstdint>

// ---------------- problem constants ----------------
constexpr int BB    = 8;
constexpr int NTOK  = 4096;   // 64x64
constexpr int CD    = 512;
constexpr int NHEAD = 8;
constexpr int HDIM  = 64;
constexpr int RP    = 8;
constexpr int MT    = 64;     // 8x8 reduced tokens
constexpr int KIM   = RP * RP * CD;   // 32768
constexpr int SPLITK = 16;

// ---------------- device scratch ----------------
__device__ float g_q[(size_t)BB * NHEAD * HDIM * NTOK];   // [b,nh,hd,n] 64MB
__device__ float g_wt512[CD * CD];                        // Wq^T / Wp^T (reused)
__device__ float g_wtc[(size_t)CD * KIM];                 // conv_w^T  64MB
__device__ float g_part[(size_t)SPLITK * BB * MT * CD];   // 16MB
__device__ float g_fmap[BB * MT * CD];
__device__ float g_ln[BB * MT * CD];
__device__ float g_kv[BB * MT * 2 * CD];
__device__ float g_attn[(size_t)BB * NTOK * CD];          // 64MB

__device__ __forceinline__ float tf32r(float x) {
    uint32_t u;
    asm("cvt.rna.tf32.f32 %0, %1;" : "=r"(u) : "f"(x));
    return __uint_as_float(u);
}

__device__ __forceinline__ void mma8(float c[4], uint32_t a0, uint32_t a1,
                                     uint32_t a2, uint32_t a3,
                                     uint32_t b0, uint32_t b1) {
    asm volatile(
        "mma.sync.aligned.m16n8k8.row.col.f32.tf32.tf32.f32 "
        "{%0,%1,%2,%3}, {%4,%5,%6,%7}, {%8,%9}, {%0,%1,%2,%3};"
        : "+f"(c[0]), "+f"(c[1]), "+f"(c[2]), "+f"(c[3])
        : "r"(a0), "r"(a1), "r"(a2), "r"(a3), "r"(b0), "r"(b1));
}

// ---------------- tf32 mma.sync GEMM ----------------
// C[M,N] = A[M,K] @ BT[N,K]^T.
// AMODE 0: A row-major.  AMODE 1: conv im2col gather from x.
// SMODE 0: plain store (+bias).  SMODE 1: split-K partial.  SMODE 2: q [b,nh,hd,n].
template <int AMODE, int SMODE>
__global__ __launch_bounds__(256, 2)
void mma_gemm(const float* __restrict__ A, const float* __restrict__ BT,
              float* __restrict__ C, int M, int N, int K, int kPerZ,
              const float* __restrict__ bias)
{
    constexpr int SK = 20;   // padded k-stride (conflict-free: 20r mod 32 tiles banks)
    __shared__ float As[2][128][SK];
    __shared__ float Bs[2][128][SK];

    const int tid = threadIdx.x;
    const int wid = tid >> 5, lid = tid & 31;
    const int gid = lid >> 2, t4 = lid & 3;
    const int wm = wid >> 2, wn = wid & 3;          // 2 x 4 warp grid
    const int n0 = blockIdx.x * 128, m0 = blockIdx.y * 128;
    const int k0 = blockIdx.z * kPerZ;
    const int nIter = kPerZ >> 4;

    const int lr = tid >> 2;          // load row base (+64 for second half)
    const int lc = (tid & 3) * 4;     // load col (k) offset

    float acc[4][4][4];
#pragma unroll
    for (int i = 0; i < 4; i++)
#pragma unroll
        for (int j = 0; j < 4; j++)
#pragma unroll
            for (int r = 0; r < 4; r++) acc[i][j][r] = 0.f;

    float4 stA[2], stB[2];

    auto ldg = [&](int it) {
        const int kt = k0 + it * 16;
#pragma unroll
        for (int i = 0; i < 2; i++) {
            const int r = lr + i * 64;
            const float* srcA;
            if (AMODE == 0) {
                srcA = A + (size_t)(m0 + r) * K + kt + lc;
            } else {
                int pg = m0 + r;                 // b*64 + patch
                int b = pg >> 6, p = pg & 63;
                int kk = kt + lc;
                int rs = kk >> 9, ci = kk & 511;
                int n = ((p >> 3) * 8 + (rs >> 3)) * 64 + (p & 7) * 8 + (rs & 7);
                srcA = A + (((size_t)((b << 12) + n)) << 9) + ci;
            }
            stA[i] = *(const float4*)srcA;
            stB[i] = *(const float4*)(BT + (size_t)(n0 + r) * K + kt + lc);
        }
    };
    auto sts = [&](int b) {
#pragma unroll
        for (int i = 0; i < 2; i++) {
            const int r = lr + i * 64;
            float4 va = stA[i], vb = stB[i];
            va.x = tf32r(va.x); va.y = tf32r(va.y); va.z = tf32r(va.z); va.w = tf32r(va.w);
            vb.x = tf32r(vb.x); vb.y = tf32r(vb.y); vb.z = tf32r(vb.z); vb.w = tf32r(vb.w);
            *(float4*)&As[b][r][lc] = va;
            *(float4*)&Bs[b][r][lc] = vb;
        }
    };

    ldg(0);
    sts(0);
    __syncthreads();

    for (int it = 0; it < nIter; it++) {
        const int buf = it & 1;
        if (it + 1 < nIter) ldg(it + 1);

#pragma unroll
        for (int ks = 0; ks < 2; ks++) {
            uint32_t af[4][4], bf[4][2];
            const int kb = ks * 8 + t4;
#pragma unroll
            for (int fm = 0; fm < 4; fm++) {
                const int m = wm * 64 + fm * 16 + gid;
                af[fm][0] = __float_as_uint(As[buf][m][kb]);
                af[fm][1] = __float_as_uint(As[buf][m + 8][kb]);
                af[fm][2] = __float_as_uint(As[buf][m][kb + 4]);
                af[fm][3] = __float_as_uint(As[buf][m + 8][kb + 4]);
            }
#pragma unroll
            for (int fn = 0; fn < 4; fn++) {
                const int n = wn * 32 + fn * 8 + gid;
                bf[fn][0] = __float_as_uint(Bs[buf][n][kb]);
                bf[fn][1] = __float_as_uint(Bs[buf][n][kb + 4]);
            }
#pragma unroll
            for (int fm = 0; fm < 4; fm++)
#pragma unroll
                for (int fn = 0; fn < 4; fn++)
                    mma8(acc[fm][fn], af[fm][0], af[fm][1], af[fm][2], af[fm][3],
                         bf[fn][0], bf[fn][1]);
        }

        if (it + 1 < nIter) sts(buf ^ 1);
        __syncthreads();
    }

    // epilogue
#pragma unroll
    for (int fm = 0; fm < 4; fm++) {
#pragma unroll
        for (int fn = 0; fn < 4; fn++) {
            const int col = n0 + wn * 32 + fn * 8 + t4 * 2;
#pragma unroll
            for (int h = 0; h < 2; h++) {         // h=0: row gid, h=1: row gid+8
                const int row = m0 + wm * 64 + fm * 16 + gid + h * 8;
                float v0 = acc[fm][fn][2 * h + 0];
                float v1 = acc[fm][fn][2 * h + 1];
                if (SMODE == 0) {
                    if (bias) { v0 += bias[col]; v1 += bias[col + 1]; }
                    float2 v = make_float2(v0, v1);
                    *(float2*)(C + (size_t)row * N + col) = v;
                } else if (SMODE == 1) {
                    float2 v = make_float2(v0, v1);
                    *(float2*)(C + (size_t)blockIdx.z * M * N + (size_t)row * N + col) = v;
                } else {
                    const int b = row >> 12, n = row & 4095;
                    const int nh0 = col & 7, hd0 = col >> 3;
                    const int nh1 = (col + 1) & 7, hd1 = (col + 1) >> 3;
                    g_q[(((size_t)(b * NHEAD + nh0) * HDIM + hd0)) * NTOK + n] = v0;
                    g_q[(((size_t)(b * NHEAD + nh1) * HDIM + hd1)) * NTOK + n] = v1;
                }
            }
        }
    }
}

// ---------------- transpose: WT[n][k] = W[k][n] ----------------
__global__ void transpose_k(const float* __restrict__ W, float* __restrict__ WT,
                            int K, int N)
{
    __shared__ float s[32][33];
    int kb = blockIdx.x * 32, nb = blockIdx.y * 32;
    int tx = threadIdx.x & 31, ty = threadIdx.x >> 5;
    for (int r = ty; r < 32; r += 8)
        s[r][tx] = W[(size_t)(kb + r) * N + nb + tx];
    __syncthreads();
    for (int r = ty; r < 32; r += 8)
        WT[(size_t)(nb + r) * K + kb + tx] = s[tx][r];
}

// ---------------- reduce split-K partials ----------------
__global__ void reduce_k()
{
    int i = blockIdx.x * 256 + threadIdx.x;
    float s = 0.f;
#pragma unroll
    for (int z = 0; z < SPLITK; z++) s += g_part[(size_t)z * BB * MT * CD + i];
    g_fmap[i] = s;
}

// ---------------- layernorm ----------------
__global__ void ln_k(const float* __restrict__ gamma, const float* __restrict__ beta)
{
    int row = blockIdx.x;
    const float* in = g_fmap + (size_t)row * CD;
    float* out = g_ln + (size_t)row * CD;
    int t = threadIdx.x;
    float a = in[t], b2 = in[t + 256];
    float s = a + b2, s2 = a * a + b2 * b2;
#pragma unroll
    for (int o = 16; o; o >>= 1) {
        s  += __shfl_down_sync(0xffffffffu, s,  o);
        s2 += __shfl_down_sync(0xffffffffu, s2, o);
    }
    __shared__ float rs[8], rs2[8];
    int w = t >> 5, l = t & 31;
    if (l == 0) { rs[w] = s; rs2[w] = s2; }
    __syncthreads();
    if (t == 0) {
        float S = 0.f, S2 = 0.f;
        for (int q2 = 0; q2 < 8; q2++) { S += rs[q2]; S2 += rs2[q2]; }
        float mu = S / (float)CD;
        float var = S2 / (float)CD - mu * mu;
        rs[0] = mu;
        rs2[0] = rsqrtf(var + 1e-3f);
    }
    __syncthreads();
    float mu = rs[0], inv = rs2[0];
    out[t]       = (a  - mu) * inv * gamma[t]       + beta[t];
    out[t + 256] = (b2 - mu) * inv * gamma[t + 256] + beta[t + 256];
}

// ---------------- small fp32 SGEMM for kv ----------------
__global__ __launch_bounds__(256)
void sgemm_kv(const float* __restrict__ A, const float* __restrict__ Bm,
              float* __restrict__ C, int M, int N, int K)
{
    constexpr int BM = 64, BN = 64, BK = 16, TM = 4, TN = 4;
    __shared__ float As[BK][BM];
    __shared__ float Bs[BK][BN];
    const int tid = threadIdx.x;
    const int bx = blockIdx.x, by = blockIdx.y;
    const int tcol = tid % (BN / TN), trow = tid / (BN / TN);
    const int aCol = (tid % 4) * 4, aRow = tid / 4;
    const int bCol = (tid % 16) * 4, bRow = tid / 16;
    const float* Ab = A + (size_t)by * BM * K;
    const float* Bb = Bm + bx * BN;
    float acc[TM][TN] = {};
    for (int kt = 0; kt < K; kt += BK) {
        float4 v = *(const float4*)(Ab + (size_t)aRow * K + kt + aCol);
        As[aCol + 0][aRow] = v.x; As[aCol + 1][aRow] = v.y;
        As[aCol + 2][aRow] = v.z; As[aCol + 3][aRow] = v.w;
        *(float4*)(&Bs[bRow][bCol]) = *(const float4*)(Bb + (size_t)(kt + bRow) * N + bCol);
        __syncthreads();
#pragma unroll
        for (int kk = 0; kk < BK; ++kk) {
            float ra[TM], rb[TN];
#pragma unroll
            for (int i = 0; i < TM; i++) ra[i] = As[kk][trow * TM + i];
#pragma unroll
            for (int j = 0; j < TN; j++) rb[j] = Bs[kk][tcol * TN + j];
#pragma unroll
            for (int i = 0; i < TM; i++)
#pragma unroll
                for (int j = 0; j < TN; j++)
                    acc[i][j] = fmaf(ra[i], rb[j], acc[i][j]);
        }
        __syncthreads();
    }
#pragma unroll
    for (int i = 0; i < TM; i++)
#pragma unroll
        for (int j = 0; j < TN; j++)
            C[(size_t)(by * BM + trow * TM + i) * N + bx * BN + tcol * TN + j] = acc[i][j];
}

// ---------------- attention: per (b,head), K/V (64x64) in SMEM ----------------
__global__ __launch_bounds__(128) void attn_k()
{
    int bh = blockIdx.y;
    int b = bh >> 3, nh = bh & 7;
    int n = blockIdx.x * 128 + threadIdx.x;

    __shared__ float Ks[MT][HDIM];
    __shared__ float Vs[MT][HDIM];
    for (int i = threadIdx.x; i < MT * HDIM / 4; i += 128) {
        int e = i * 4;
        int m = e >> 6, hd = e & 63;
        const float* src = g_kv + ((size_t)(b * MT + m)) * (2 * CD) + nh * HDIM + hd;
        *(float4*)&Ks[m][hd] = *(const float4*)src;
        *(float4*)&Vs[m][hd] = *(const float4*)(src + CD);
    }
    __syncthreads();

    const float* qb = g_q + (size_t)bh * HDIM * NTOK + n;
    float q[HDIM];
#pragma unroll
    for (int d = 0; d < HDIM; d++) q[d] = qb[(size_t)d * NTOK];

    float mx = -1e30f, sum = 0.f;
    float o[HDIM];
#pragma unroll
    for (int d = 0; d < HDIM; d++) o[d] = 0.f;

    for (int m = 0; m < MT; m++) {
        float s = 0.f;
#pragma unroll
        for (int d = 0; d < HDIM; d++) s = fmaf(q[d], Ks[m][d], s);
        s *= 0.125f;
        float nm = fmaxf(mx, s);
        float corr = expf(mx - nm);
        float wgt = expf(s - nm);
        sum = sum * corr + wgt;
#pragma unroll
        for (int d = 0; d < HDIM; d++) o[d] = o[d] * corr + wgt * Vs[m][d];
        mx = nm;
    }
    float inv = 1.f / sum;

    float* dst = g_attn + ((size_t)(b * NTOK + n)) * CD + nh * HDIM;
#pragma unroll
    for (int i = 0; i < HDIM / 4; i++) {
        float4 v;
        v.x = o[4 * i] * inv; v.y = o[4 * i + 1] * inv;
        v.z = o[4 * i + 2] * inv; v.w = o[4 * i + 3] * inv;
        *(float4*)(dst + 4 * i) = v;
    }
}

// ---------------- launch ----------------
extern "C" void kernel_launch(void* const* d_in, const int* in_sizes, int n_in,
                              void* d_out, int out_size)
{
    const float* x     = (const float*)d_in[0];
    const float* Wq    = (const float*)d_in[1];
    const float* Wkv   = (const float*)d_in[2];
    const float* convw = (const float*)d_in[3];
    const float* gamma = (const float*)d_in[4];
    const float* beta  = (const float*)d_in[5];
    const float* Wp    = (const float*)d_in[6];
    const float* bp    = (const float*)d_in[7];
    float* out = (float*)d_out;

    float *wt512, *wtc, *part, *ln, *kv, *attn;
    cudaGetSymbolAddress((void**)&wt512, g_wt512);
    cudaGetSymbolAddress((void**)&wtc,   g_wtc);
    cudaGetSymbolAddress((void**)&part,  g_part);
    cudaGetSymbolAddress((void**)&ln,    g_ln);
    cudaGetSymbolAddress((void**)&kv,    g_kv);
    cudaGetSymbolAddress((void**)&attn,  g_attn);

    // 1. Wq^T ; q = x @ Wq -> g_q [b,nh,hd,n]
    transpose_k<<<dim3(CD / 32, CD / 32), 256>>>(Wq, wt512, CD, CD);
    mma_gemm<0, 2><<<dim3(CD / 128, BB * NTOK / 128), 256>>>(
        x, wt512, nullptr, BB * NTOK, CD, CD, CD, nullptr);

    // 2. conv_w^T ; conv GEMM (direct im2col gather from x), split-K
    transpose_k<<<dim3(KIM / 32, CD / 32), 256>>>(convw, wtc, KIM, CD);
    mma_gemm<1, 1><<<dim3(CD / 128, BB * MT / 128, SPLITK), 256>>>(
        x, wtc, part, BB * MT, CD, KIM, KIM / SPLITK, nullptr);
    reduce_k<<<(BB * MT * CD) / 256, 256>>>();

    // 3. layernorm + kv
    ln_k<<<BB * MT, 256>>>(gamma, beta);
    sgemm_kv<<<dim3((2 * CD) / 64, (BB * MT) / 64), 256>>>(ln, Wkv, kv, BB * MT, 2 * CD, CD);

    // 4. attention
    attn_k<<<dim3(NTOK / 128, BB * NHEAD), 128>>>();

    // 5. Wp^T ; out = attn @ Wp + bp
    transpose_k<<<dim3(CD / 32, CD / 32), 256>>>(Wp, wt512, CD, CD);
    mma_gemm<0, 0><<<dim3(CD / 128, BB * NTOK / 128), 256>>>(
        attn, wt512, out, BB * NTOK, CD, CD, CD, bp);
}

// round 4
// speedup vs baseline: 2.5026x; 1.1839x over previous
#include <cuda_runtime.h>
#include <math.h>
#include <cstdint>

// ---------------- problem constants ----------------
constexpr int BB    = 8;
constexpr int NTOK  = 4096;   // 64x64
constexpr int CD    = 512;
constexpr int NHEAD = 8;
constexpr int HDIM  = 64;
constexpr int MT    = 64;     // 8x8 reduced tokens
constexpr int KIM   = 64 * CD;        // 32768
constexpr int SPLITK = 32;

// gemm engine
constexpr int STAGES = 4;
constexpr int ASZ = 128 * 20;         // floats / stage
constexpr int BSZ = 16 * 136;
constexpr int SMEM_BYTES = STAGES * (ASZ + BSZ) * 4;   // 75776

// ---------------- device scratch ----------------
__device__ float g_q[(size_t)BB * NHEAD * HDIM * NTOK];   // [b,nh,hd,n]
__device__ float g_xc[(size_t)BB * NTOK * CD];            // tf32-rounded x
__device__ float g_cwr[(size_t)KIM * CD];                 // tf32-rounded conv_w
__device__ float g_wqr[CD * CD];
__device__ float g_wpr[CD * CD];
__device__ float g_part[(size_t)SPLITK * BB * MT * CD];
__device__ float g_ln[BB * MT * CD];
__device__ float g_kv[BB * MT * 2 * CD];
__device__ float g_attn[(size_t)BB * NTOK * CD];

__device__ __forceinline__ float tf32r(float x) {
    uint32_t u;
    asm("cvt.rna.tf32.f32 %0, %1;" : "=r"(u) : "f"(x));
    return __uint_as_float(u);
}
__device__ __forceinline__ uint32_t smem_u32(const void* p) {
    uint32_t a;
    asm("{ .reg .u64 t; cvta.to.shared.u64 t, %1; cvt.u32.u64 %0, t; }" : "=r"(a) : "l"(p));
    return a;
}
#define CP16(dst, src) \
    asm volatile("cp.async.cg.shared.global [%0], [%1], 16;" :: "r"(dst), "l"(src))
#define CP_COMMIT() asm volatile("cp.async.commit_group;" ::: "memory")
#define CP_WAIT2()  asm volatile("cp.async.wait_group 2;" ::: "memory")

__device__ __forceinline__ void mma8(float c[4], uint32_t a0, uint32_t a1,
                                     uint32_t a2, uint32_t a3,
                                     uint32_t b0, uint32_t b1) {
    asm volatile(
        "mma.sync.aligned.m16n8k8.row.col.f32.tf32.tf32.f32 "
        "{%0,%1,%2,%3}, {%4,%5,%6,%7}, {%8,%9}, {%0,%1,%2,%3};"
        : "+f"(c[0]), "+f"(c[1]), "+f"(c[2]), "+f"(c[3])
        : "r"(a0), "r"(a1), "r"(a2), "r"(a3), "r"(b0), "r"(b1));
}

// packed f32x2 helpers (base sm_100+ PTX)
__device__ __forceinline__ uint64_t pk2(float lo, float hi) {
    uint64_t r; asm("mov.b64 %0, {%1,%2};" : "=l"(r) : "f"(lo), "f"(hi)); return r;
}
__device__ __forceinline__ void upk2(uint64_t v, float& lo, float& hi) {
    asm("mov.b64 {%0,%1}, %2;" : "=f"(lo), "=f"(hi) : "l"(v));
}
__device__ __forceinline__ uint64_t fma2(uint64_t a, uint64_t b, uint64_t c) {
    uint64_t d; asm("fma.rn.f32x2 %0, %1, %2, %3;" : "=l"(d) : "l"(a), "l"(b), "l"(c));
    return d;
}
__device__ __forceinline__ float ex2f(float x) {
    float r; asm("ex2.approx.ftz.f32 %0, %1;" : "=f"(r) : "f"(x)); return r;
}

// ---------------- tf32 mma.sync GEMM, 4-stage cp.async pipeline ----------------
// C[M,N] = A[M,K] @ B[K,N]; A,B pre-rounded to tf32. B consumed in native [k][n].
// AMODE 0: A row-major.  AMODE 1: conv im2col gather from g_xc.
// SMODE 0: store +bias.  SMODE 1: split-K partial.  SMODE 2: q [b,nh,hd,n].
template <int AMODE, int SMODE>
__global__ __launch_bounds__(256, 2)
void mma_gemm(const float* __restrict__ A, const float* __restrict__ B,
              float* __restrict__ C, int M, int N, int K, int kPerZ,
              const float* __restrict__ bias)
{
    extern __shared__ float sm[];
    float* As = sm;                       // [STAGES][128][20]
    float* Bs = sm + STAGES * ASZ;        // [STAGES][16][136]
    const uint32_t smA = smem_u32(As);
    const uint32_t smB = smem_u32(Bs);

    const int tid = threadIdx.x;
    const int wid = tid >> 5, lid = tid & 31;
    const int gid = lid >> 2, t4 = lid & 3;
    const int wm = wid >> 2, wn = wid & 3;          // 2 x 4 warp grid (64x32 tiles)
    const int n0 = blockIdx.x * 128, m0 = blockIdx.y * 128;
    const int k0 = blockIdx.z * kPerZ;
    const int nIter = kPerZ >> 4;

    float acc[4][4][4];
#pragma unroll
    for (int i = 0; i < 4; i++)
#pragma unroll
        for (int j = 0; j < 4; j++)
#pragma unroll
            for (int r = 0; r < 4; r++) acc[i][j][r] = 0.f;

    auto load_tile = [&](int it) {
        const int stage = it & (STAGES - 1);
        const int kt = k0 + it * 16;
        const uint32_t ab = smA + stage * (ASZ * 4);
        const uint32_t bb = smB + stage * (BSZ * 4);
#pragma unroll
        for (int j = 0; j < 2; j++) {
            int qd = tid + j * 256;
            int r = qd >> 2, lc = (qd & 3) * 4;
            const float* src;
            if (AMODE == 0) {
                src = A + (size_t)(m0 + r) * K + kt + lc;
            } else {
                int pg = m0 + r;                 // b*64 + patch
                int b = pg >> 6, p = pg & 63;
                int kk = kt + lc;
                int rs = kk >> 9, ci = kk & 511;
                int n = ((p >> 3) * 8 + (rs >> 3)) * 64 + (p & 7) * 8 + (rs & 7);
                src = A + (((size_t)((b << 12) + n)) << 9) + ci;
            }
            CP16(ab + (uint32_t)(r * 20 + lc) * 4, src);
        }
#pragma unroll
        for (int j = 0; j < 2; j++) {
            int qd = tid + j * 256;
            int k = qd >> 5, nn = (qd & 31) * 4;
            CP16(bb + (uint32_t)(k * 136 + nn) * 4,
                 B + (size_t)(kt + k) * N + n0 + nn);
        }
        CP_COMMIT();
    };

#pragma unroll
    for (int it = 0; it < STAGES - 1; it++) {
        if (it < nIter) load_tile(it); else CP_COMMIT();
    }

    for (int it = 0; it < nIter; it++) {
        CP_WAIT2();
        __syncthreads();
        if (it + STAGES - 1 < nIter) load_tile(it + STAGES - 1);
        else CP_COMMIT();

        const int stage = it & (STAGES - 1);
        const float* Ab = As + stage * ASZ;
        const float* Bb = Bs + stage * BSZ;
#pragma unroll
        for (int ks = 0; ks < 2; ks++) {
            uint32_t af[4][4], bf[4][2];
            const int kb = ks * 8 + t4;
#pragma unroll
            for (int fm = 0; fm < 4; fm++) {
                const int m = wm * 64 + fm * 16 + gid;
                af[fm][0] = __float_as_uint(Ab[m * 20 + kb]);
                af[fm][1] = __float_as_uint(Ab[(m + 8) * 20 + kb]);
                af[fm][2] = __float_as_uint(Ab[m * 20 + kb + 4]);
                af[fm][3] = __float_as_uint(Ab[(m + 8) * 20 + kb + 4]);
            }
#pragma unroll
            for (int fn = 0; fn < 4; fn++) {
                const int nn = wn * 32 + fn * 8 + gid;
                bf[fn][0] = __float_as_uint(Bb[kb * 136 + nn]);
                bf[fn][1] = __float_as_uint(Bb[(kb + 4) * 136 + nn]);
            }
#pragma unroll
            for (int fm = 0; fm < 4; fm++)
#pragma unroll
                for (int fn = 0; fn < 4; fn++)
                    mma8(acc[fm][fn], af[fm][0], af[fm][1], af[fm][2], af[fm][3],
                         bf[fn][0], bf[fn][1]);
        }
    }

    // epilogue
#pragma unroll
    for (int fm = 0; fm < 4; fm++) {
#pragma unroll
        for (int fn = 0; fn < 4; fn++) {
            const int col = n0 + wn * 32 + fn * 8 + t4 * 2;
#pragma unroll
            for (int h = 0; h < 2; h++) {
                const int row = m0 + wm * 64 + fm * 16 + gid + h * 8;
                float v0 = acc[fm][fn][2 * h + 0];
                float v1 = acc[fm][fn][2 * h + 1];
                if (SMODE == 0) {
                    if (bias) { v0 += bias[col]; v1 += bias[col + 1]; }
                    *(float2*)(C + (size_t)row * N + col) = make_float2(v0, v1);
                } else if (SMODE == 1) {
                    *(float2*)(C + (size_t)blockIdx.z * M * N + (size_t)row * N + col) =
                        make_float2(v0, v1);
                } else {
                    const int b = row >> 12, n = row & 4095;
                    const int nh0 = col & 7, hd0 = col >> 3;
                    const int nh1 = (col + 1) & 7, hd1 = (col + 1) >> 3;
                    g_q[(((size_t)(b * NHEAD + nh0) * HDIM + hd0)) * NTOK + n] = v0;
                    g_q[(((size_t)(b * NHEAD + nh1) * HDIM + hd1)) * NTOK + n] = v1;
                }
            }
        }
    }
}

// ---------------- tf32 rounding copy ----------------
__global__ void round4_k(const float* __restrict__ src, float* __restrict__ dst, int n4)
{
    int i = blockIdx.x * 256 + threadIdx.x;
    if (i >= n4) return;
    float4 v = *(const float4*)(src + 4 * (size_t)i);
    v.x = tf32r(v.x); v.y = tf32r(v.y); v.z = tf32r(v.z); v.w = tf32r(v.w);
    *(float4*)(dst + 4 * (size_t)i) = v;
}

// ---------------- fused split-K reduce + layernorm ----------------
__global__ void reduce_ln_k(const float* __restrict__ gamma, const float* __restrict__ beta)
{
    int row = blockIdx.x;
    int t = threadIdx.x;
    const float* p = g_part + (size_t)row * CD;
    float a = 0.f, b2 = 0.f;
#pragma unroll
    for (int z = 0; z < SPLITK; z++) {
        a  += p[(size_t)z * (BB * MT * CD) + t];
        b2 += p[(size_t)z * (BB * MT * CD) + t + 256];
    }
    float s = a + b2, s2 = a * a + b2 * b2;
#pragma unroll
    for (int o = 16; o; o >>= 1) {
        s  += __shfl_down_sync(0xffffffffu, s,  o);
        s2 += __shfl_down_sync(0xffffffffu, s2, o);
    }
    __shared__ float rs[8], rs2[8];
    int w = t >> 5, l = t & 31;
    if (l == 0) { rs[w] = s; rs2[w] = s2; }
    __syncthreads();
    if (t == 0) {
        float S = 0.f, S2 = 0.f;
        for (int q2 = 0; q2 < 8; q2++) { S += rs[q2]; S2 += rs2[q2]; }
        float mu = S / (float)CD;
        float var = S2 / (float)CD - mu * mu;
        rs[0] = mu;
        rs2[0] = rsqrtf(var + 1e-3f);
    }
    __syncthreads();
    float mu = rs[0], inv = rs2[0];
    float* out = g_ln + (size_t)row * CD;
    out[t]       = (a  - mu) * inv * gamma[t]       + beta[t];
    out[t + 256] = (b2 - mu) * inv * gamma[t + 256] + beta[t + 256];
}

// ---------------- small fp32 SGEMM for kv ----------------
__global__ __launch_bounds__(256)
void sgemm_kv(const float* __restrict__ A, const float* __restrict__ Bm,
              float* __restrict__ C, int M, int N, int K)
{
    constexpr int BM = 64, BN = 64, BK = 16, TM = 4, TN = 4;
    __shared__ float As[BK][BM];
    __shared__ float Bs[BK][BN];
    const int tid = threadIdx.x;
    const int bx = blockIdx.x, by = blockIdx.y;
    const int tcol = tid % (BN / TN), trow = tid / (BN / TN);
    const int aCol = (tid % 4) * 4, aRow = tid / 4;
    const int bCol = (tid % 16) * 4, bRow = tid / 16;
    const float* Ab = A + (size_t)by * BM * K;
    const float* Bb = Bm + bx * BN;
    float acc[TM][TN] = {};
    for (int kt = 0; kt < K; kt += BK) {
        float4 v = *(const float4*)(Ab + (size_t)aRow * K + kt + aCol);
        As[aCol + 0][aRow] = v.x; As[aCol + 1][aRow] = v.y;
        As[aCol + 2][aRow] = v.z; As[aCol + 3][aRow] = v.w;
        *(float4*)(&Bs[bRow][bCol]) = *(const float4*)(Bb + (size_t)(kt + bRow) * N + bCol);
        __syncthreads();
#pragma unroll
        for (int kk = 0; kk < BK; ++kk) {
            float ra[TM], rb[TN];
#pragma unroll
            for (int i = 0; i < TM; i++) ra[i] = As[kk][trow * TM + i];
#pragma unroll
            for (int j = 0; j < TN; j++) rb[j] = Bs[kk][tcol * TN + j];
#pragma unroll
            for (int i = 0; i < TM; i++)
#pragma unroll
                for (int j = 0; j < TN; j++)
                    acc[i][j] = fmaf(ra[i], rb[j], acc[i][j]);
        }
        __syncthreads();
    }
#pragma unroll
    for (int i = 0; i < TM; i++)
#pragma unroll
        for (int j = 0; j < TN; j++)
            C[(size_t)(by * BM + trow * TM + i) * N + bx * BN + tcol * TN + j] = acc[i][j];
}

// ---------------- attention: packed f32x2 + MUFU ex2, no online-softmax ----------------
__global__ __launch_bounds__(128) void attn_k()
{
    int bh = blockIdx.y;
    int b = bh >> 3, nh = bh & 7;
    int n = blockIdx.x * 128 + threadIdx.x;

    __shared__ float Ks[MT][HDIM];
    __shared__ float Vs[MT][HDIM];
    for (int i = threadIdx.x; i < MT * HDIM / 4; i += 128) {
        int e = i * 4;
        int m = e >> 6, hd = e & 63;
        const float* src = g_kv + ((size_t)(b * MT + m)) * (2 * CD) + nh * HDIM + hd;
        *(float4*)&Ks[m][hd] = *(const float4*)src;
        *(float4*)&Vs[m][hd] = *(const float4*)(src + CD);
    }
    __syncthreads();

    // q in [b,nh,hd,n]: coalesced across lanes; pack d-pairs
    const float* qb = g_q + (size_t)bh * HDIM * NTOK + n;
    uint64_t q2[HDIM / 2];
#pragma unroll
    for (int d = 0; d < HDIM / 2; d++)
        q2[d] = pk2(qb[(size_t)(2 * d) * NTOK], qb[(size_t)(2 * d + 1) * NTOK]);

    uint64_t o2[HDIM / 2];
    const uint64_t zero = pk2(0.f, 0.f);
#pragma unroll
    for (int d = 0; d < HDIM / 2; d++) o2[d] = zero;

    constexpr float SC = 0.125f * 1.4426950408889634f;   // scale * log2(e)
    float sum = 0.f;

    for (int m = 0; m < MT; m++) {
        const uint64_t* K2 = (const uint64_t*)&Ks[m][0];
        const uint64_t* V2 = (const uint64_t*)&Vs[m][0];
        uint64_t acc = zero;
#pragma unroll
        for (int d = 0; d < HDIM / 2; d++) acc = fma2(q2[d], K2[d], acc);
        float lo, hi;
        upk2(acc, lo, hi);
        float w = ex2f((lo + hi) * SC);
        sum += w;
        uint64_t w2 = pk2(w, w);
#pragma unroll
        for (int d = 0; d < HDIM / 2; d++) o2[d] = fma2(w2, V2[d], o2[d]);
    }
    float inv = 1.f / sum;

    // store tf32-rounded (consumed by the final tf32 GEMM)
    float* dst = g_attn + ((size_t)(b * NTOK + n)) * CD + nh * HDIM;
#pragma unroll
    for (int d = 0; d < HDIM / 2; d++) {
        float lo, hi;
        upk2(o2[d], lo, hi);
        float2 v = make_float2(tf32r(lo * inv), tf32r(hi * inv));
        *(float2*)(dst + 2 * d) = v;
    }
}

// ---------------- launch ----------------
extern "C" void kernel_launch(void* const* d_in, const int* in_sizes, int n_in,
                              void* d_out, int out_size)
{
    const float* x     = (const float*)d_in[0];
    const float* Wq    = (const float*)d_in[1];
    const float* Wkv   = (const float*)d_in[2];
    const float* convw = (const float*)d_in[3];
    const float* gamma = (const float*)d_in[4];
    const float* beta  = (const float*)d_in[5];
    const float* Wp    = (const float*)d_in[6];
    const float* bp    = (const float*)d_in[7];
    float* out = (float*)d_out;

    float *xc, *cwr, *wqr, *wpr, *part, *ln, *kv, *attn;
    cudaGetSymbolAddress((void**)&xc,   g_xc);
    cudaGetSymbolAddress((void**)&cwr,  g_cwr);
    cudaGetSymbolAddress((void**)&wqr,  g_wqr);
    cudaGetSymbolAddress((void**)&wpr,  g_wpr);
    cudaGetSymbolAddress((void**)&part, g_part);
    cudaGetSymbolAddress((void**)&ln,   g_ln);
    cudaGetSymbolAddress((void**)&kv,   g_kv);
    cudaGetSymbolAddress((void**)&attn, g_attn);

    cudaFuncSetAttribute(mma_gemm<0, 0>, cudaFuncAttributeMaxDynamicSharedMemorySize, SMEM_BYTES);
    cudaFuncSetAttribute(mma_gemm<0, 2>, cudaFuncAttributeMaxDynamicSharedMemorySize, SMEM_BYTES);
    cudaFuncSetAttribute(mma_gemm<1, 1>, cudaFuncAttributeMaxDynamicSharedMemorySize, SMEM_BYTES);

    // 0. tf32-round inputs
    {
        int n4x = BB * NTOK * CD / 4;
        round4_k<<<(n4x + 255) / 256, 256>>>(x, xc, n4x);
        int n4c = KIM * CD / 4;
        round4_k<<<(n4c + 255) / 256, 256>>>(convw, cwr, n4c);
        int n4w = CD * CD / 4;
        round4_k<<<(n4w + 255) / 256, 256>>>(Wq, wqr, n4w);
        round4_k<<<(n4w + 255) / 256, 256>>>(Wp, wpr, n4w);
    }

    // 1. q = x @ Wq -> g_q [b,nh,hd,n]
    mma_gemm<0, 2><<<dim3(CD / 128, BB * NTOK / 128), 256, SMEM_BYTES>>>(
        xc, wqr, nullptr, BB * NTOK, CD, CD, CD, nullptr);

    // 2. conv GEMM (direct im2col gather), split-K=32
    mma_gemm<1, 1><<<dim3(CD / 128, BB * MT / 128, SPLITK), 256, SMEM_BYTES>>>(
        xc, cwr, part, BB * MT, CD, KIM, KIM / SPLITK, nullptr);
    reduce_ln_k<<<BB * MT, 256>>>(gamma, beta);

    // 3. kv = ln @ Wkv (exact fp32)
    sgemm_kv<<<dim3((2 * CD) / 64, (BB * MT) / 64), 256>>>(ln, Wkv, kv, BB * MT, 2 * CD, CD);

    // 4. attention
    attn_k<<<dim3(NTOK / 128, BB * NHEAD), 128>>>();

    // 5. out = attn @ Wp + bp
    mma_gemm<0, 0><<<dim3(CD / 128, BB * NTOK / 128), 256, SMEM_BYTES>>>(
        attn, wpr, out, BB * NTOK, CD, CD, CD, bp);
}

// round 5
// speedup vs baseline: 3.5974x; 1.4375x over previous
#include <cuda_runtime.h>
#include <cuda_fp16.h>
#include <math.h>
#include <cstdint>

// ---------------- problem constants ----------------
constexpr int BB    = 8;
constexpr int NTOK  = 4096;   // 64x64
constexpr int CD    = 512;
constexpr int NHEAD = 8;
constexpr int HDIM  = 64;
constexpr int MT    = 64;     // 8x8 reduced tokens
constexpr int KIM   = 64 * CD;        // 32768
constexpr int SPLITK = 32;

// gemm engine (fp16 operands, fp32 accum)
constexpr int BK = 32;
constexpr int PA = 40;                 // A pitch in halves (80 B, conflict-free)
constexpr int PB = 136;                // B pitch in halves (272 B, conflict-free)
constexpr int STAGES = 4;
constexpr int ASZ = 128 * PA;          // halves / stage
constexpr int BSZ = BK * PB;
constexpr int SMEM_BYTES = STAGES * (ASZ + BSZ) * 2;   // 75776

// ---------------- device scratch ----------------
__device__ float  g_q[(size_t)BB * NHEAD * HDIM * NTOK];   // [b,nh,hd,n]
__device__ __half g_xc[(size_t)BB * NTOK * CD];            // fp16 x
__device__ __half g_cwr[(size_t)KIM * CD];                 // fp16 conv_w
__device__ __half g_wqr[CD * CD];
__device__ __half g_wpr[CD * CD];
__device__ float  g_part[(size_t)SPLITK * BB * MT * CD];
__device__ float  g_ln[BB * MT * CD];
__device__ float  g_kv[BB * MT * 2 * CD];
__device__ __half g_attn[(size_t)BB * NTOK * CD];

__device__ __forceinline__ uint32_t smem_u32(const void* p) {
    uint32_t a;
    asm("{ .reg .u64 t; cvta.to.shared.u64 t, %1; cvt.u32.u64 %0, t; }" : "=r"(a) : "l"(p));
    return a;
}
#define CP16(dst, src) \
    asm volatile("cp.async.cg.shared.global [%0], [%1], 16;" :: "r"(dst), "l"(src))
#define CP_COMMIT() asm volatile("cp.async.commit_group;" ::: "memory")
#define CP_WAIT2()  asm volatile("cp.async.wait_group 2;" ::: "memory")

#define LDSM_X4(r0, r1, r2, r3, a) \
    asm volatile("ldmatrix.sync.aligned.m8n8.x4.shared.b16 {%0,%1,%2,%3}, [%4];" \
        : "=r"(r0), "=r"(r1), "=r"(r2), "=r"(r3) : "r"(a))
#define LDSM_X4T(r0, r1, r2, r3, a) \
    asm volatile("ldmatrix.sync.aligned.m8n8.x4.trans.shared.b16 {%0,%1,%2,%3}, [%4];" \
        : "=r"(r0), "=r"(r1), "=r"(r2), "=r"(r3) : "r"(a))

__device__ __forceinline__ void mma16(float c[4], uint32_t a0, uint32_t a1,
                                      uint32_t a2, uint32_t a3,
                                      uint32_t b0, uint32_t b1) {
    asm volatile(
        "mma.sync.aligned.m16n8k16.row.col.f32.f16.f16.f32 "
        "{%0,%1,%2,%3}, {%4,%5,%6,%7}, {%8,%9}, {%0,%1,%2,%3};"
        : "+f"(c[0]), "+f"(c[1]), "+f"(c[2]), "+f"(c[3])
        : "r"(a0), "r"(a1), "r"(a2), "r"(a3), "r"(b0), "r"(b1));
}

// packed f32x2 helpers
__device__ __forceinline__ uint64_t pk2(float lo, float hi) {
    uint64_t r; asm("mov.b64 %0, {%1,%2};" : "=l"(r) : "f"(lo), "f"(hi)); return r;
}
__device__ __forceinline__ void upk2(uint64_t v, float& lo, float& hi) {
    asm("mov.b64 {%0,%1}, %2;" : "=f"(lo), "=f"(hi) : "l"(v));
}
__device__ __forceinline__ uint64_t fma2(uint64_t a, uint64_t b, uint64_t c) {
    uint64_t d; asm("fma.rn.f32x2 %0, %1, %2, %3;" : "=l"(d) : "l"(a), "l"(b), "l"(c));
    return d;
}
__device__ __forceinline__ float ex2f(float x) {
    float r; asm("ex2.approx.ftz.f32 %0, %1;" : "=f"(r) : "f"(x)); return r;
}

// ---------------- fp16 mma.sync GEMM, 4-stage cp.async, ldmatrix ----------------
// C[M,N] = A[M,K] @ B[K,N]; A,B fp16. B consumed native [k][n].
// AMODE 0: A row-major.  AMODE 1: conv im2col gather from g_xc.
// SMODE 0: store fp32 +bias.  SMODE 1: split-K partial.  SMODE 2: q fp32 [b,nh,hd,n].
template <int AMODE, int SMODE>
__global__ __launch_bounds__(256, 2)
void mma_gemm(const __half* __restrict__ A, const __half* __restrict__ B,
              float* __restrict__ C, int M, int N, int K, int kPerZ,
              const float* __restrict__ bias)
{
    extern __shared__ __half sm[];
    __half* As = sm;                       // [STAGES][128][PA]
    __half* Bs = sm + STAGES * ASZ;        // [STAGES][BK][PB]
    const uint32_t smA = smem_u32(As);
    const uint32_t smB = smem_u32(Bs);

    const int tid = threadIdx.x;
    const int wid = tid >> 5, lid = tid & 31;
    const int gid = lid >> 2, t4 = lid & 3;
    const int wm = wid >> 2, wn = wid & 3;          // 2 x 4 warps (64x32 tiles)
    const int n0 = blockIdx.x * 128, m0 = blockIdx.y * 128;
    const int k0 = blockIdx.z * kPerZ;
    const int nIter = kPerZ / BK;

    float acc[4][4][4];
#pragma unroll
    for (int i = 0; i < 4; i++)
#pragma unroll
        for (int j = 0; j < 4; j++)
#pragma unroll
            for (int r = 0; r < 4; r++) acc[i][j][r] = 0.f;

    auto load_tile = [&](int it) {
        const int stage = it & (STAGES - 1);
        const int kt = k0 + it * BK;
        const uint32_t ab = smA + stage * (ASZ * 2);
        const uint32_t bb = smB + stage * (BSZ * 2);
#pragma unroll
        for (int j = 0; j < 2; j++) {          // A: 512 chunks of 8 halves
            int cid = tid + j * 256;
            int r = cid >> 2, kc = (cid & 3) * 8;
            const __half* src;
            if (AMODE == 0) {
                src = A + (size_t)(m0 + r) * K + kt + kc;
            } else {
                int pg = m0 + r;                 // b*64 + patch
                int b = pg >> 6, p = pg & 63;
                int kk = kt + kc;
                int rs = kk >> 9, ci = kk & 511;
                int n = ((p >> 3) * 8 + (rs >> 3)) * 64 + (p & 7) * 8 + (rs & 7);
                src = A + (((size_t)((b << 12) + n)) << 9) + ci;
            }
            CP16(ab + (uint32_t)(r * PA + kc) * 2, src);
        }
#pragma unroll
        for (int j = 0; j < 2; j++) {          // B: 512 chunks
            int cid = tid + j * 256;
            int k = cid >> 4, nc = (cid & 15) * 8;
            CP16(bb + (uint32_t)(k * PB + nc) * 2,
                 B + (size_t)(kt + k) * N + n0 + nc);
        }
        CP_COMMIT();
    };

#pragma unroll
    for (int it = 0; it < STAGES - 1; it++) {
        if (it < nIter) load_tile(it); else CP_COMMIT();
    }

    // ldmatrix lane address components (constant per thread)
    const int aRow = (lid & 15);               // + m-base
    const int aCol = 8 * (lid >> 4);           // + kstep base
    const int bRow = (lid & 7) + 8 * ((lid >> 3) & 1);  // + kstep base
    const int bCol = 8 * (lid >> 4);           // + n-base

    for (int it = 0; it < nIter; it++) {
        CP_WAIT2();
        __syncthreads();
        if (it + STAGES - 1 < nIter) load_tile(it + STAGES - 1);
        else CP_COMMIT();

        const int stage = it & (STAGES - 1);
        const uint32_t Ab = smA + stage * (ASZ * 2);
        const uint32_t Bb = smB + stage * (BSZ * 2);
#pragma unroll
        for (int ks = 0; ks < 2; ks++) {
            const int kb = ks * 16;
            uint32_t af[4][4], bf[4][2];
#pragma unroll
            for (int fm = 0; fm < 4; fm++) {
                const int m = wm * 64 + fm * 16 + aRow;
                LDSM_X4(af[fm][0], af[fm][1], af[fm][2], af[fm][3],
                        Ab + (uint32_t)(m * PA + kb + aCol) * 2);
            }
#pragma unroll
            for (int g = 0; g < 2; g++) {
                const int nn = wn * 32 + g * 16 + bCol;
                LDSM_X4T(bf[2 * g][0], bf[2 * g][1], bf[2 * g + 1][0], bf[2 * g + 1][1],
                         Bb + (uint32_t)((kb + bRow) * PB + nn) * 2);
            }
#pragma unroll
            for (int fm = 0; fm < 4; fm++)
#pragma unroll
                for (int fn = 0; fn < 4; fn++)
                    mma16(acc[fm][fn], af[fm][0], af[fm][1], af[fm][2], af[fm][3],
                          bf[fn][0], bf[fn][1]);
        }
    }

    // epilogue
#pragma unroll
    for (int fm = 0; fm < 4; fm++) {
#pragma unroll
        for (int fn = 0; fn < 4; fn++) {
            const int col = n0 + wn * 32 + fn * 8 + t4 * 2;
#pragma unroll
            for (int h = 0; h < 2; h++) {
                const int row = m0 + wm * 64 + fm * 16 + gid + h * 8;
                float v0 = acc[fm][fn][2 * h + 0];
                float v1 = acc[fm][fn][2 * h + 1];
                if (SMODE == 0) {
                    if (bias) { v0 += bias[col]; v1 += bias[col + 1]; }
                    *(float2*)(C + (size_t)row * N + col) = make_float2(v0, v1);
                } else if (SMODE == 1) {
                    *(float2*)(C + (size_t)blockIdx.z * M * N + (size_t)row * N + col) =
                        make_float2(v0, v1);
                } else {
                    const int b = row >> 12, n = row & 4095;
                    const int nh0 = col & 7, hd0 = col >> 3;
                    const int nh1 = (col + 1) & 7, hd1 = (col + 1) >> 3;
                    g_q[(((size_t)(b * NHEAD + nh0) * HDIM + hd0)) * NTOK + n] = v0;
                    g_q[(((size_t)(b * NHEAD + nh1) * HDIM + hd1)) * NTOK + n] = v1;
                }
            }
        }
    }
}

// ---------------- fp32 -> fp16 conversion (8 elems/thread) ----------------
__global__ void round_h_k(const float* __restrict__ src, __half* __restrict__ dst, int n8)
{
    int i = blockIdx.x * 256 + threadIdx.x;
    if (i >= n8) return;
    float4 v0 = *(const float4*)(src + 8 * (size_t)i);
    float4 v1 = *(const float4*)(src + 8 * (size_t)i + 4);
    __half2* d = (__half2*)(dst + 8 * (size_t)i);
    d[0] = __floats2half2_rn(v0.x, v0.y);
    d[1] = __floats2half2_rn(v0.z, v0.w);
    d[2] = __floats2half2_rn(v1.x, v1.y);
    d[3] = __floats2half2_rn(v1.z, v1.w);
}

// ---------------- fused split-K reduce + layernorm ----------------
__global__ void reduce_ln_k(const float* __restrict__ gamma, const float* __restrict__ beta)
{
    int row = blockIdx.x;
    int t = threadIdx.x;
    const float* p = g_part + (size_t)row * CD;
    float a = 0.f, b2 = 0.f;
#pragma unroll
    for (int z = 0; z < SPLITK; z++) {
        a  += p[(size_t)z * (BB * MT * CD) + t];
        b2 += p[(size_t)z * (BB * MT * CD) + t + 256];
    }
    float s = a + b2, s2 = a * a + b2 * b2;
#pragma unroll
    for (int o = 16; o; o >>= 1) {
        s  += __shfl_down_sync(0xffffffffu, s,  o);
        s2 += __shfl_down_sync(0xffffffffu, s2, o);
    }
    __shared__ float rs[8], rs2[8];
    int w = t >> 5, l = t & 31;
    if (l == 0) { rs[w] = s; rs2[w] = s2; }
    __syncthreads();
    if (t == 0) {
        float S = 0.f, S2 = 0.f;
        for (int q2 = 0; q2 < 8; q2++) { S += rs[q2]; S2 += rs2[q2]; }
        float mu = S / (float)CD;
        float var = S2 / (float)CD - mu * mu;
        rs[0] = mu;
        rs2[0] = rsqrtf(var + 1e-3f);
    }
    __syncthreads();
    float mu = rs[0], inv = rs2[0];
    float* out = g_ln + (size_t)row * CD;
    out[t]       = (a  - mu) * inv * gamma[t]       + beta[t];
    out[t + 256] = (b2 - mu) * inv * gamma[t + 256] + beta[t + 256];
}

// ---------------- small fp32 SGEMM for kv ----------------
__global__ __launch_bounds__(256)
void sgemm_kv(const float* __restrict__ A, const float* __restrict__ Bm,
              float* __restrict__ C, int M, int N, int K)
{
    constexpr int BM = 64, BN = 64, BKs = 16, TM = 4, TN = 4;
    __shared__ float As[BKs][BM];
    __shared__ float Bs[BKs][BN];
    const int tid = threadIdx.x;
    const int bx = blockIdx.x, by = blockIdx.y;
    const int tcol = tid % (BN / TN), trow = tid / (BN / TN);
    const int aCol = (tid % 4) * 4, aRow = tid / 4;
    const int bCol = (tid % 16) * 4, bRow = tid / 16;
    const float* Ab = A + (size_t)by * BM * K;
    const float* Bb = Bm + bx * BN;
    float acc[TM][TN] = {};
    for (int kt = 0; kt < K; kt += BKs) {
        float4 v = *(const float4*)(Ab + (size_t)aRow * K + kt + aCol);
        As[aCol + 0][aRow] = v.x; As[aCol + 1][aRow] = v.y;
        As[aCol + 2][aRow] = v.z; As[aCol + 3][aRow] = v.w;
        *(float4*)(&Bs[bRow][bCol]) = *(const float4*)(Bb + (size_t)(kt + bRow) * N + bCol);
        __syncthreads();
#pragma unroll
        for (int kk = 0; kk < BKs; ++kk) {
            float ra[TM], rb[TN];
#pragma unroll
            for (int i = 0; i < TM; i++) ra[i] = As[kk][trow * TM + i];
#pragma unroll
            for (int j = 0; j < TN; j++) rb[j] = Bs[kk][tcol * TN + j];
#pragma unroll
            for (int i = 0; i < TM; i++)
#pragma unroll
                for (int j = 0; j < TN; j++)
                    acc[i][j] = fmaf(ra[i], rb[j], acc[i][j]);
        }
        __syncthreads();
    }
#pragma unroll
    for (int i = 0; i < TM; i++)
#pragma unroll
        for (int j = 0; j < TN; j++)
            C[(size_t)(by * BM + trow * TM + i) * N + bx * BN + tcol * TN + j] = acc[i][j];
}

// ---------------- attention ----------------
__global__ __launch_bounds__(128) void attn_k()
{
    int bh = blockIdx.y;
    int b = bh >> 3, nh = bh & 7;
    int n = blockIdx.x * 128 + threadIdx.x;

    __shared__ float Ks[MT][HDIM];
    __shared__ float Vs[MT][HDIM];
    for (int i = threadIdx.x; i < MT * HDIM / 4; i += 128) {
        int e = i * 4;
        int m = e >> 6, hd = e & 63;
        const float* src = g_kv + ((size_t)(b * MT + m)) * (2 * CD) + nh * HDIM + hd;
        *(float4*)&Ks[m][hd] = *(const float4*)src;
        *(float4*)&Vs[m][hd] = *(const float4*)(src + CD);
    }
    __syncthreads();

    const float* qb = g_q + (size_t)bh * HDIM * NTOK + n;
    uint64_t q2[HDIM / 2];
#pragma unroll
    for (int d = 0; d < HDIM / 2; d++)
        q2[d] = pk2(qb[(size_t)(2 * d) * NTOK], qb[(size_t)(2 * d + 1) * NTOK]);

    uint64_t o2[HDIM / 2];
    const uint64_t zero = pk2(0.f, 0.f);
#pragma unroll
    for (int d = 0; d < HDIM / 2; d++) o2[d] = zero;

    constexpr float SC = 0.125f * 1.4426950408889634f;
    float sum = 0.f;

    for (int m = 0; m < MT; m++) {
        const uint64_t* K2 = (const uint64_t*)&Ks[m][0];
        const uint64_t* V2 = (const uint64_t*)&Vs[m][0];
        uint64_t acc = zero;
#pragma unroll
        for (int d = 0; d < HDIM / 2; d++) acc = fma2(q2[d], K2[d], acc);
        float lo, hi;
        upk2(acc, lo, hi);
        float w = ex2f((lo + hi) * SC);
        sum += w;
        uint64_t w2 = pk2(w, w);
#pragma unroll
        for (int d = 0; d < HDIM / 2; d++) o2[d] = fma2(w2, V2[d], o2[d]);
    }
    float inv = 1.f / sum;

    __half* dst = g_attn + ((size_t)(b * NTOK + n)) * CD + nh * HDIM;
#pragma unroll
    for (int d = 0; d < HDIM / 2; d++) {
        float lo, hi;
        upk2(o2[d], lo, hi);
        *(__half2*)(dst + 2 * d) = __floats2half2_rn(lo * inv, hi * inv);
    }
}

// ---------------- launch ----------------
extern "C" void kernel_launch(void* const* d_in, const int* in_sizes, int n_in,
                              void* d_out, int out_size)
{
    const float* x     = (const float*)d_in[0];
    const float* Wq    = (const float*)d_in[1];
    const float* Wkv   = (const float*)d_in[2];
    const float* convw = (const float*)d_in[3];
    const float* gamma = (const float*)d_in[4];
    const float* beta  = (const float*)d_in[5];
    const float* Wp    = (const float*)d_in[6];
    const float* bp    = (const float*)d_in[7];
    float* out = (float*)d_out;

    __half *xc, *cwr, *wqr, *wpr, *attnp;
    float *part, *ln, *kv;
    cudaGetSymbolAddress((void**)&xc,    g_xc);
    cudaGetSymbolAddress((void**)&cwr,   g_cwr);
    cudaGetSymbolAddress((void**)&wqr,   g_wqr);
    cudaGetSymbolAddress((void**)&wpr,   g_wpr);
    cudaGetSymbolAddress((void**)&part,  g_part);
    cudaGetSymbolAddress((void**)&ln,    g_ln);
    cudaGetSymbolAddress((void**)&kv,    g_kv);
    cudaGetSymbolAddress((void**)&attnp, g_attn);

    cudaFuncSetAttribute(mma_gemm<0, 0>, cudaFuncAttributeMaxDynamicSharedMemorySize, SMEM_BYTES);
    cudaFuncSetAttribute(mma_gemm<0, 2>, cudaFuncAttributeMaxDynamicSharedMemorySize, SMEM_BYTES);
    cudaFuncSetAttribute(mma_gemm<1, 1>, cudaFuncAttributeMaxDynamicSharedMemorySize, SMEM_BYTES);

    // 0. convert inputs to fp16
    {
        int n8x = BB * NTOK * CD / 8;
        round_h_k<<<(n8x + 255) / 256, 256>>>(x, xc, n8x);
        int n8c = KIM * CD / 8;
        round_h_k<<<(n8c + 255) / 256, 256>>>(convw, cwr, n8c);
        int n8w = CD * CD / 8;
        round_h_k<<<(n8w + 255) / 256, 256>>>(Wq, wqr, n8w);
        round_h_k<<<(n8w + 255) / 256, 256>>>(Wp, wpr, n8w);
    }

    // 1. q = x @ Wq -> g_q [b,nh,hd,n] (fp32)
    mma_gemm<0, 2><<<dim3(CD / 128, BB * NTOK / 128), 256, SMEM_BYTES>>>(
        xc, wqr, nullptr, BB * NTOK, CD, CD, CD, nullptr);

    // 2. conv GEMM (direct im2col gather), split-K=32
    mma_gemm<1, 1><<<dim3(CD / 128, BB * MT / 128, SPLITK), 256, SMEM_BYTES>>>(
        xc, cwr, part, BB * MT, CD, KIM, KIM / SPLITK, nullptr);
    reduce_ln_k<<<BB * MT, 256>>>(gamma, beta);

    // 3. kv = ln @ Wkv (exact fp32)
    sgemm_kv<<<dim3((2 * CD) / 64, (BB * MT) / 64), 256>>>(ln, Wkv, kv, BB * MT, 2 * CD, CD);

    // 4. attention -> g_attn (fp16)
    attn_k<<<dim3(NTOK / 128, BB * NHEAD), 128>>>();

    // 5. out = attn @ Wp + bp
    mma_gemm<0, 0><<<dim3(CD / 128, BB * NTOK / 128), 256, SMEM_BYTES>>>(
        attnp, wpr, out, BB * NTOK, CD, CD, CD, bp);
}